// round 8
// baseline (speedup 1.0000x reference)
#include <cuda_runtime.h>
#include <math.h>

#define NE   16
#define NU   8
#define NA   4
#define NSV  256
#define NPV  32
#define NFB  4
#define NDET 16
#define SVO  832   // 3*256 + 2*32

// shared layout (floats)
#define OFF_SV    0        // 16*256 = 4096
#define OFF_PV    4096     // 256*32 = 8192   (s_in + detS alias here)
#define OFF_MU    12288    // 256             (logd/sign/env alias here at the end)
#define OFF_MD    12544    // 256
#define OFF_PU    12800    // 16*32 = 512
#define OFF_PD    13312    // 512
#define OFF_COM   13824    // 512             (r_s/a_s alias here early)
#define SMEM_FLOATS 14336
#define SMEM_BYTES  (SMEM_FLOATS * 4)

__device__ __forceinline__ float tanh_fast(float x) {
    float e = __expf(2.0f * x);
    return 1.0f - __fdividef(2.0f, e + 1.0f);
}

__global__ void __launch_bounds__(256, 3) ansatz_kernel(
    const float* __restrict__ r,    const float* __restrict__ a,
    const float* __restrict__ sW0,  const float* __restrict__ sb0,
    const float* __restrict__ sW,   const float* __restrict__ sb,
    const float* __restrict__ pW0,  const float* __restrict__ pb0,
    const float* __restrict__ pW,   const float* __restrict__ pb,
    const float* __restrict__ vW,   const float* __restrict__ vb,
    const float* __restrict__ wuW,  const float* __restrict__ wub,
    const float* __restrict__ wdW,  const float* __restrict__ wdb,
    const float* __restrict__ wfW,  float* __restrict__ out)
{
    extern __shared__ float sm[];
    float* s_v  = sm + OFF_SV;
    float* p_v  = sm + OFF_PV;
    float* mu   = sm + OFF_MU;
    float* md   = sm + OFF_MD;
    float* pu   = sm + OFF_PU;
    float* pd   = sm + OFF_PD;
    float* com  = sm + OFF_COM;

    float* s_in = sm + OFF_PV;          // alias, dead before p_v written
    float* r_s  = sm + OFF_COM;         // alias, dead before com written
    float* a_s  = sm + OFF_COM + 48;
    float* detS   = sm + OFF_PV;        // alias, p_v dead by orbital phase
    float* logd_s = sm + OFF_MU;
    float* sign_s = sm + OFF_MU + 32;
    float* env    = sm + OFF_MU + 64;

    const int t = threadIdx.x;
    const int b = blockIdx.x;

    if (t < 48)              r_s[t]      = r[b * 48 + t];
    if (t >= 64 && t < 76)   a_s[t - 64] = a[t - 64];
    __syncthreads();

    // ---------------- embedding: s_in ----------------
    {
        int e = t >> 4, f = t & 15, atom = f >> 2, comp = f & 3;
        float dx = r_s[e*3+0] - a_s[atom*3+0];
        float dy = r_s[e*3+1] - a_s[atom*3+1];
        float dz = r_s[e*3+2] - a_s[atom*3+2];
        float v;
        if      (comp == 0) v = dx;
        else if (comp == 1) v = dy;
        else if (comp == 2) v = dz;
        else                v = sqrtf(dx*dx + dy*dy + dz*dz);
        s_in[t] = v;
    }
    __syncthreads();

    // ---------------- stats for layer 0 ----------------
    if (t < 16) {
        float s = 0.f;
        #pragma unroll
        for (int e = 0; e < NU; e++) s += s_in[e*16 + t];
        mu[t] = s * 0.125f;
    } else if (t < 32) {
        int f = t - 16; float s = 0.f;
        #pragma unroll
        for (int e = NU; e < NE; e++) s += s_in[e*16 + f];
        md[f] = s * 0.125f;
    } else if (t < 160) {
        int idx = t - 32;
        int half = idx >> 6;
        idx &= 63;
        int j = idx >> 2, c = idx & 3;
        int ib = half * 8;
        float rjx = r_s[j*3+0], rjy = r_s[j*3+1], rjz = r_s[j*3+2];
        float s = 0.f;
        #pragma unroll
        for (int ii = 0; ii < 8; ii++) {
            int i = ib + ii;
            float dx = rjx - r_s[i*3+0];
            float dy = rjy - r_s[i*3+1];
            float dz = rjz - r_s[i*3+2];
            float v;
            if      (c == 0) v = dx;
            else if (c == 1) v = dy;
            else if (c == 2) v = dz;
            else {
                float o = (i == j) ? 1.f : 0.f;
                float ex = dx + o, ey = dy + o, ez = dz + o;
                v = sqrtf(ex*ex + ey*ey + ez*ez);
            }
            s += v;
        }
        if (half == 0) pu[j*4 + c] = s * 0.125f;
        else           pd[j*4 + c] = s * 0.125f;
    }
    __syncthreads();

    // ---------------- layer 0, s-stream ----------------
    float smu, smd;
    {
        const int c = t;
        float common = sb0[c];
        #pragma unroll
        for (int k = 0; k < 16; k++)
            common += mu[k] * sW0[(16 + k)*NSV + c] + md[k] * sW0[(32 + k)*NSV + c];
        float acc[NE];
        #pragma unroll
        for (int e = 0; e < NE; e++) acc[e] = 0.f;
        #pragma unroll
        for (int k = 0; k < 16; k++) {
            float w = sW0[k*NSV + c];
            #pragma unroll
            for (int e = 0; e < NE; e++) acc[e] += s_in[e*16 + k] * w;
        }
        #pragma unroll
        for (int k = 0; k < 4; k++) {
            float wA = sW0[(48 + k)*NSV + c];
            float wB = sW0[(52 + k)*NSV + c];
            #pragma unroll
            for (int e = 0; e < NE; e++)
                acc[e] += pu[e*4 + k] * wA + pd[e*4 + k] * wB;
        }
        smu = 0.f; smd = 0.f;
        #pragma unroll
        for (int e = 0; e < NE; e++) {
            float v = tanh_fast(acc[e] + common);
            s_v[e*NSV + c] = v;
            if (e < NU) smu += v; else smd += v;
        }
    }
    __syncthreads();   // s_in reads done; p_v may be written

    // ---------------- layer 0, p-stream ----------------
    {
        const int c2 = t & 31, wp = t >> 5;
        float w0 = pW0[0*NPV + c2], w1 = pW0[1*NPV + c2];
        float w2 = pW0[2*NPV + c2], w3 = pW0[3*NPV + c2];
        const float pbias = pb0[c2];
        float puA = 0.f, puB = 0.f, pdA = 0.f, pdB = 0.f;
        for (int pr = wp; pr < 256; pr += 8) {
            int i = pr >> 4, j = pr & 15;
            float dx = r_s[j*3+0] - r_s[i*3+0];
            float dy = r_s[j*3+1] - r_s[i*3+1];
            float dz = r_s[j*3+2] - r_s[i*3+2];
            float o = (i == j) ? 1.f : 0.f;
            float ex = dx + o, ey = dy + o, ez = dz + o;
            float len = sqrtf(ex*ex + ey*ey + ez*ez);
            float v = tanh_fast(pbias + dx*w0 + dy*w1 + dz*w2 + len*w3);
            p_v[pr*NPV + c2] = v;
            bool jA = ((pr >> 3) & 1) == 0;
            if (i < NU) { if (jA) puA += v; else puB += v; }
            else        { if (jA) pdA += v; else pdB += v; }
        }
        pu[wp*NPV + c2]       = puA * 0.125f;
        pu[(wp+8)*NPV + c2]   = puB * 0.125f;
        pd[wp*NPV + c2]       = pdA * 0.125f;
        pd[(wp+8)*NPV + c2]   = pdB * 0.125f;
        mu[t] = smu * 0.125f;
        md[t] = smd * 0.125f;
    }
    __syncthreads();

    // ---------------- residual layers + final v layer ----------------
    // thread -> (electron half, column quad, k half)
    const int kh    = t & 1;            // k-half (shfl partner = lane^1)
    const int q     = (t >> 1) & 63;    // column quad
    const int eh    = t >> 7;           // electron half
    const int cA    = q * 4;
    const int ebase = eh * 8;
    const int kbase = kh * 128;
    const int myc   = cA + kh * 2;      // 2 columns this lane writes back

    for (int L = 0; L <= NFB; L++) {
        const bool isV = (L == NFB);
        const float* W    = isV ? vW : (sW + (size_t)L * SVO * NSV);
        const float* bias = isV ? vb : (sb + L * NSV);

        float puA = 0.f, puB = 0.f, pdA = 0.f, pdB = 0.f;
        if (!isV) {
            // p-stream residual layer (lane-private columns, in-place)
            const int c2 = t & 31, wp = t >> 5;
            const float* PW = pW + L * NPV * NPV + c2;
            float pw[32];
            #pragma unroll
            for (int k = 0; k < 32; k++) pw[k] = PW[k*NPV];
            const float pbias = pb[L*NPV + c2];
            for (int pr = wp; pr < 256; pr += 8) {
                float pacc = pbias;
                #pragma unroll
                for (int k = 0; k < 32; k += 4) {
                    float4 v4 = *(const float4*)(p_v + pr*NPV + k);
                    pacc += v4.x*pw[k] + v4.y*pw[k+1] + v4.z*pw[k+2] + v4.w*pw[k+3];
                }
                float v = tanh_fast(pacc) + p_v[pr*NPV + c2];
                p_v[pr*NPV + c2] = v;
                bool jA = ((pr >> 3) & 1) == 0;
                if ((pr >> 4) < NU) { if (jA) puA += v; else puB += v; }
                else                { if (jA) pdA += v; else pdB += v; }
            }
        }

        // ---- common matvec: (eh -> mu/md block) x (kh -> k half), 4 cols ----
        float c4x = 0.f, c4y = 0.f, c4z = 0.f, c4w = 0.f;
        {
            const float* statv = (eh ? md : mu) + kbase;
            const float* Wblk  = W + (size_t)(256 + eh*256 + kbase) * NSV + cA;
            for (int k = 0; k < 128; k += 4) {
                float4 m4 = *(const float4*)(statv + k);
                float4 w0 = *(const float4*)(Wblk + (k+0)*NSV);
                float4 w1 = *(const float4*)(Wblk + (k+1)*NSV);
                float4 w2 = *(const float4*)(Wblk + (k+2)*NSV);
                float4 w3 = *(const float4*)(Wblk + (k+3)*NSV);
                c4x += m4.x*w0.x + m4.y*w1.x + m4.z*w2.x + m4.w*w3.x;
                c4y += m4.x*w0.y + m4.y*w1.y + m4.z*w2.y + m4.w*w3.y;
                c4z += m4.x*w0.z + m4.y*w1.z + m4.z*w2.z + m4.w*w3.z;
                c4w += m4.x*w0.w + m4.y*w1.w + m4.z*w2.w + m4.w*w3.w;
            }
            if (eh == 0 && kh == 0) {
                float4 b4 = *(const float4*)(bias + cA);
                c4x += b4.x; c4y += b4.y; c4z += b4.z; c4w += b4.w;
            }
            // combine kh halves
            c4x += __shfl_xor_sync(0xffffffffu, c4x, 1);
            c4y += __shfl_xor_sync(0xffffffffu, c4y, 1);
            c4z += __shfl_xor_sync(0xffffffffu, c4z, 1);
            c4w += __shfl_xor_sync(0xffffffffu, c4w, 1);
            if (kh == 0) { float2 cv; cv.x = c4x; cv.y = c4y;
                           *(float2*)(com + (eh << 8) + cA) = cv; }
            else         { float2 cv; cv.x = c4z; cv.y = c4w;
                           *(float2*)(com + (eh << 8) + cA + 2) = cv; }
        }

        // ---- main GEMM: 8 electrons x 4 adjacent cols x half-k ----
        float acc0[8], acc1[8], acc2[8], acc3[8];
        #pragma unroll
        for (int e = 0; e < 8; e++) { acc0[e]=0.f; acc1[e]=0.f; acc2[e]=0.f; acc3[e]=0.f; }
        {
            const float* Wc = W + (size_t)kbase*NSV + cA;
            const float* sv = s_v + ebase*NSV + kbase;
            for (int k = 0; k < 128; k += 4) {
                float4 w0 = *(const float4*)(Wc + (k+0)*NSV);
                float4 w1 = *(const float4*)(Wc + (k+1)*NSV);
                float4 w2 = *(const float4*)(Wc + (k+2)*NSV);
                float4 w3 = *(const float4*)(Wc + (k+3)*NSV);
                #pragma unroll
                for (int e = 0; e < 8; e++) {
                    float4 s4 = *(const float4*)(sv + e*NSV + k);
                    acc0[e] += s4.x*w0.x + s4.y*w1.x + s4.z*w2.x + s4.w*w3.x;
                    acc1[e] += s4.x*w0.y + s4.y*w1.y + s4.z*w2.y + s4.w*w3.y;
                    acc2[e] += s4.x*w0.z + s4.y*w1.z + s4.z*w2.z + s4.w*w3.z;
                    acc3[e] += s4.x*w0.w + s4.y*w1.w + s4.z*w2.w + s4.w*w3.w;
                }
            }
        }
        // ---- pu/pd block: kh=0 -> pu, kh=1 -> pd ----
        {
            const float* Wp = W + (size_t)(768 + kh*32) * NSV + cA;
            const float* pv = (kh ? pd : pu) + ebase*NPV;
            for (int k = 0; k < 32; k += 4) {
                float4 w0 = *(const float4*)(Wp + (k+0)*NSV);
                float4 w1 = *(const float4*)(Wp + (k+1)*NSV);
                float4 w2 = *(const float4*)(Wp + (k+2)*NSV);
                float4 w3 = *(const float4*)(Wp + (k+3)*NSV);
                #pragma unroll
                for (int e = 0; e < 8; e++) {
                    float4 a4 = *(const float4*)(pv + e*NPV + k);
                    acc0[e] += a4.x*w0.x + a4.y*w1.x + a4.z*w2.x + a4.w*w3.x;
                    acc1[e] += a4.x*w0.y + a4.y*w1.y + a4.z*w2.y + a4.w*w3.y;
                    acc2[e] += a4.x*w0.z + a4.y*w1.z + a4.z*w2.z + a4.w*w3.z;
                    acc3[e] += a4.x*w0.w + a4.y*w1.w + a4.z*w2.w + a4.w*w3.w;
                }
            }
        }
        // ---- combine k halves (partner lane) ----
        #pragma unroll
        for (int e = 0; e < 8; e++) {
            acc0[e] += __shfl_xor_sync(0xffffffffu, acc0[e], 1);
            acc1[e] += __shfl_xor_sync(0xffffffffu, acc1[e], 1);
            acc2[e] += __shfl_xor_sync(0xffffffffu, acc2[e], 1);
            acc3[e] += __shfl_xor_sync(0xffffffffu, acc3[e], 1);
        }

        __syncthreads();   // all s_v/pu/pd/mu/md reads + com writes complete

        // ---- writeback: each lane owns 2 columns (myc) ----
        {
            float2 cm0 = *(const float2*)(com + myc);
            float2 cm1 = *(const float2*)(com + 256 + myc);
            const float cmA = cm0.x + cm1.x;
            const float cmB = cm0.y + cm1.y;
            float sA = 0.f, sB = 0.f;
            if (!isV) {
                #pragma unroll
                for (int e = 0; e < 8; e++) {
                    float aA = kh ? acc2[e] : acc0[e];
                    float aB = kh ? acc3[e] : acc1[e];
                    float* dst = s_v + (ebase+e)*NSV + myc;
                    float2 old = *(const float2*)dst;
                    float2 nv;
                    nv.x = tanh_fast(aA + cmA) + old.x;
                    nv.y = tanh_fast(aB + cmB) + old.y;
                    *(float2*)dst = nv;
                    sA += nv.x; sB += nv.y;
                }
                float* statdst = eh ? md : mu;
                float2 sv2; sv2.x = sA * 0.125f; sv2.y = sB * 0.125f;
                *(float2*)(statdst + myc) = sv2;
                const int c2 = t & 31, wp = t >> 5;
                pu[wp*NPV + c2]     = puA * 0.125f;
                pu[(wp+8)*NPV + c2] = puB * 0.125f;
                pd[wp*NPV + c2]     = pdA * 0.125f;
                pd[(wp+8)*NPV + c2] = pdB * 0.125f;
            } else {
                #pragma unroll
                for (int e = 0; e < 8; e++) {
                    float aA = kh ? acc2[e] : acc0[e];
                    float aB = kh ? acc3[e] : acc1[e];
                    float2 nv;
                    nv.x = tanh_fast(aA + cmA);
                    nv.y = tanh_fast(aB + cmB);
                    *(float2*)(s_v + (ebase+e)*NSV + myc) = nv;
                }
                if (t < 16) {
                    const float* rg = r + b*48 + t*3;
                    float ex = rg[0], ey = rg[1], ez = rg[2];
                    float s = 0.f;
                    #pragma unroll
                    for (int atom = 0; atom < NA; atom++) {
                        float dx = ex - a[atom*3+0];
                        float dy = ey - a[atom*3+1];
                        float dz = ez - a[atom*3+2];
                        s += __expf(-sqrtf(dx*dx + dy*dy + dz*dz));
                    }
                    env[t] = s;
                }
            }
        }
        __syncthreads();
    }
    // p_v dead; detS aliases its storage.

    // ---------------- orbitals: (spin, col pair, k half) ----------------
    {
        const int osp = t >> 7;           // spin
        const int okh = t & 1;            // k half
        const int ocp = (t >> 1) & 63;    // col pair within 128
        const int ocA = ocp * 2;
        const float* W    = osp ? wdW : wuW;
        const float* bias = osp ? wdb : wub;
        const int eb2 = osp * 8;
        const int okb = okh * 128;

        float oa0[8], oa1[8];
        #pragma unroll
        for (int ii = 0; ii < 8; ii++) { oa0[ii] = 0.f; oa1[ii] = 0.f; }
        const float* Wc2 = W + (size_t)okb * 128 + ocA;
        const float* sv2 = s_v + eb2*NSV + okb;
        for (int k = 0; k < 128; k += 4) {
            float2 w0 = *(const float2*)(Wc2 + (k+0)*128);
            float2 w1 = *(const float2*)(Wc2 + (k+1)*128);
            float2 w2 = *(const float2*)(Wc2 + (k+2)*128);
            float2 w3 = *(const float2*)(Wc2 + (k+3)*128);
            #pragma unroll
            for (int ii = 0; ii < 8; ii++) {
                float4 s4 = *(const float4*)(sv2 + ii*NSV + k);
                oa0[ii] += s4.x*w0.x + s4.y*w1.x + s4.z*w2.x + s4.w*w3.x;
                oa1[ii] += s4.x*w0.y + s4.y*w1.y + s4.z*w2.y + s4.w*w3.y;
            }
        }
        #pragma unroll
        for (int ii = 0; ii < 8; ii++) {
            oa0[ii] += __shfl_xor_sync(0xffffffffu, oa0[ii], 1);
            oa1[ii] += __shfl_xor_sync(0xffffffffu, oa1[ii], 1);
        }
        const int col = ocA + okh;
        const int d = col & 15, j = col >> 4;
        const int detIdx = osp * NDET + d;
        const float bs = bias[col];
        #pragma unroll
        for (int ii = 0; ii < 8; ii++) {
            float av = okh ? oa1[ii] : oa0[ii];
            detS[detIdx*65 + ii*8 + j] = (av + bs) * env[eb2 + ii];
        }
    }
    __syncthreads();

    // ---------------- slogdet: 8x8 LU with partial pivoting ----------------
    if (t < 32) {
        float* M = detS + t * 65;
        float sg = 1.f, ld = 0.f;
        for (int k = 0; k < 8; k++) {
            int p = k; float best = fabsf(M[k*8 + k]);
            for (int rr2 = k + 1; rr2 < 8; rr2++) {
                float v = fabsf(M[rr2*8 + k]);
                if (v > best) { best = v; p = rr2; }
            }
            if (p != k) {
                for (int cc = 0; cc < 8; cc++) {
                    float tmp = M[k*8 + cc]; M[k*8 + cc] = M[p*8 + cc]; M[p*8 + cc] = tmp;
                }
                sg = -sg;
            }
            float piv = M[k*8 + k];
            if (piv < 0.f) sg = -sg;
            ld += logf(fabsf(piv));
            float inv = 1.f / piv;
            for (int rr2 = k + 1; rr2 < 8; rr2++) {
                float f = M[rr2*8 + k] * inv;
                for (int cc = k + 1; cc < 8; cc++) M[rr2*8 + cc] -= f * M[k*8 + cc];
            }
        }
        logd_s[t] = ld; sign_s[t] = sg;
    }
    __syncthreads();

    // ---------------- combine ----------------
    if (t == 0) {
        float lds[NDET], sgs[NDET], m = -1e30f;
        #pragma unroll
        for (int d = 0; d < NDET; d++) {
            lds[d] = logd_s[d] + logd_s[NDET + d];
            sgs[d] = sign_s[d] * sign_s[NDET + d];
            if (lds[d] > m) m = lds[d];
        }
        float sum = 0.f;
        #pragma unroll
        for (int d = 0; d < NDET; d++)
            sum += sgs[d] * expf(lds[d] - m) * wfW[d];
        out[b] = logf(fabsf(sum)) + m;
    }
}

extern "C" void kernel_launch(void* const* d_in, const int* in_sizes, int n_in,
                              void* d_out, int out_size)
{
    const float* r   = (const float*)d_in[0];
    const float* a   = (const float*)d_in[1];
    const float* sW0 = (const float*)d_in[2];
    const float* sb0 = (const float*)d_in[3];
    const float* sW  = (const float*)d_in[4];
    const float* sb  = (const float*)d_in[5];
    const float* pW0 = (const float*)d_in[6];
    const float* pb0 = (const float*)d_in[7];
    const float* pW  = (const float*)d_in[8];
    const float* pb  = (const float*)d_in[9];
    const float* vW  = (const float*)d_in[10];
    const float* vb  = (const float*)d_in[11];
    const float* wuW = (const float*)d_in[12];
    const float* wub = (const float*)d_in[13];
    const float* wdW = (const float*)d_in[14];
    const float* wdb = (const float*)d_in[15];
    const float* wfW = (const float*)d_in[16];
    float* out = (float*)d_out;

    const int B = in_sizes[0] / (NE * 3);

    cudaFuncSetAttribute(ansatz_kernel,
                         cudaFuncAttributeMaxDynamicSharedMemorySize, SMEM_BYTES);
    ansatz_kernel<<<B, 256, SMEM_BYTES>>>(r, a, sW0, sb0, sW, sb, pW0, pb0,
                                          pW, pb, vW, vb, wuW, wub, wdW, wdb,
                                          wfW, out);
}

// round 9
// speedup vs baseline: 1.0881x; 1.0881x over previous
#include <cuda_runtime.h>
#include <math.h>

#define NE   16
#define NU   8
#define NA   4
#define NSV  256
#define NPV  32
#define NFB  4
#define NDET 16
#define SVO  832   // 3*256 + 2*32

// shared layout (floats)
#define OFF_SV    0        // 16*256 = 4096
#define OFF_PV    4096     // 256*32 = 8192   (s_in + detS alias here)
#define OFF_MU    12288    // 256             (logd/sign/env alias here at the end)
#define OFF_MD    12544    // 256
#define OFF_PU    12800    // 16*32 = 512
#define OFF_PD    13312    // 512
#define OFF_COM   13824    // 512             (r_s/a_s alias here early)
#define SMEM_FLOATS 14336
#define SMEM_BYTES  (SMEM_FLOATS * 4)

__device__ __forceinline__ float tanh_fast(float x) {
    float e = __expf(2.0f * x);
    return 1.0f - __fdividef(2.0f, e + 1.0f);
}

__global__ void __launch_bounds__(256, 4) ansatz_kernel(
    const float* __restrict__ r,    const float* __restrict__ a,
    const float* __restrict__ sW0,  const float* __restrict__ sb0,
    const float* __restrict__ sW,   const float* __restrict__ sb,
    const float* __restrict__ pW0,  const float* __restrict__ pb0,
    const float* __restrict__ pW,   const float* __restrict__ pb,
    const float* __restrict__ vW,   const float* __restrict__ vb,
    const float* __restrict__ wuW,  const float* __restrict__ wub,
    const float* __restrict__ wdW,  const float* __restrict__ wdb,
    const float* __restrict__ wfW,  float* __restrict__ out)
{
    extern __shared__ float sm[];
    float* s_v  = sm + OFF_SV;
    float* p_v  = sm + OFF_PV;
    float* mu   = sm + OFF_MU;
    float* md   = sm + OFF_MD;
    float* pu   = sm + OFF_PU;
    float* pd   = sm + OFF_PD;
    float* com  = sm + OFF_COM;

    float* s_in = sm + OFF_PV;          // alias, dead before p_v written
    float* r_s  = sm + OFF_COM;         // alias, dead before com written
    float* a_s  = sm + OFF_COM + 48;
    float* detS   = sm + OFF_PV;        // alias, p_v dead by orbital phase
    float* logd_s = sm + OFF_MU;
    float* sign_s = sm + OFF_MU + 32;
    float* env    = sm + OFF_MU + 64;

    const int t = threadIdx.x;
    const int b = blockIdx.x;

    if (t < 48)              r_s[t]      = r[b * 48 + t];
    if (t >= 64 && t < 76)   a_s[t - 64] = a[t - 64];
    __syncthreads();

    // ---------------- embedding: s_in ----------------
    {
        int e = t >> 4, f = t & 15, atom = f >> 2, comp = f & 3;
        float dx = r_s[e*3+0] - a_s[atom*3+0];
        float dy = r_s[e*3+1] - a_s[atom*3+1];
        float dz = r_s[e*3+2] - a_s[atom*3+2];
        float v;
        if      (comp == 0) v = dx;
        else if (comp == 1) v = dy;
        else if (comp == 2) v = dz;
        else                v = sqrtf(dx*dx + dy*dy + dz*dz);
        s_in[t] = v;
    }
    __syncthreads();

    // ---------------- stats for layer 0 ----------------
    if (t < 16) {
        float s = 0.f;
        #pragma unroll
        for (int e = 0; e < NU; e++) s += s_in[e*16 + t];
        mu[t] = s * 0.125f;
    } else if (t < 32) {
        int f = t - 16; float s = 0.f;
        #pragma unroll
        for (int e = NU; e < NE; e++) s += s_in[e*16 + f];
        md[f] = s * 0.125f;
    } else if (t < 160) {
        int idx = t - 32;
        int half = idx >> 6;
        idx &= 63;
        int j = idx >> 2, c = idx & 3;
        int ib = half * 8;
        float rjx = r_s[j*3+0], rjy = r_s[j*3+1], rjz = r_s[j*3+2];
        float s = 0.f;
        #pragma unroll
        for (int ii = 0; ii < 8; ii++) {
            int i = ib + ii;
            float dx = rjx - r_s[i*3+0];
            float dy = rjy - r_s[i*3+1];
            float dz = rjz - r_s[i*3+2];
            float v;
            if      (c == 0) v = dx;
            else if (c == 1) v = dy;
            else if (c == 2) v = dz;
            else {
                float o = (i == j) ? 1.f : 0.f;
                float ex = dx + o, ey = dy + o, ez = dz + o;
                v = sqrtf(ex*ex + ey*ey + ez*ez);
            }
            s += v;
        }
        if (half == 0) pu[j*4 + c] = s * 0.125f;
        else           pd[j*4 + c] = s * 0.125f;
    }
    __syncthreads();

    // ---------------- layer 0, s-stream ----------------
    float smu, smd;
    {
        const int c = t;
        float common = sb0[c];
        #pragma unroll
        for (int k = 0; k < 16; k++)
            common += mu[k] * sW0[(16 + k)*NSV + c] + md[k] * sW0[(32 + k)*NSV + c];
        float acc[NE];
        #pragma unroll
        for (int e = 0; e < NE; e++) acc[e] = 0.f;
        #pragma unroll
        for (int k = 0; k < 16; k++) {
            float w = sW0[k*NSV + c];
            #pragma unroll
            for (int e = 0; e < NE; e++) acc[e] += s_in[e*16 + k] * w;
        }
        #pragma unroll
        for (int k = 0; k < 4; k++) {
            float wA = sW0[(48 + k)*NSV + c];
            float wB = sW0[(52 + k)*NSV + c];
            #pragma unroll
            for (int e = 0; e < NE; e++)
                acc[e] += pu[e*4 + k] * wA + pd[e*4 + k] * wB;
        }
        smu = 0.f; smd = 0.f;
        #pragma unroll
        for (int e = 0; e < NE; e++) {
            float v = tanh_fast(acc[e] + common);
            s_v[e*NSV + c] = v;
            if (e < NU) smu += v; else smd += v;
        }
    }
    __syncthreads();   // s_in reads done; p_v may be written

    // ---------------- layer 0, p-stream ----------------
    {
        const int c2 = t & 31, wp = t >> 5;
        float w0 = pW0[0*NPV + c2], w1 = pW0[1*NPV + c2];
        float w2 = pW0[2*NPV + c2], w3 = pW0[3*NPV + c2];
        const float pbias = pb0[c2];
        float puA = 0.f, puB = 0.f, pdA = 0.f, pdB = 0.f;
        for (int pr = wp; pr < 256; pr += 8) {
            int i = pr >> 4, j = pr & 15;
            float dx = r_s[j*3+0] - r_s[i*3+0];
            float dy = r_s[j*3+1] - r_s[i*3+1];
            float dz = r_s[j*3+2] - r_s[i*3+2];
            float o = (i == j) ? 1.f : 0.f;
            float ex = dx + o, ey = dy + o, ez = dz + o;
            float len = sqrtf(ex*ex + ey*ey + ez*ez);
            float v = tanh_fast(pbias + dx*w0 + dy*w1 + dz*w2 + len*w3);
            p_v[pr*NPV + c2] = v;
            bool jA = ((pr >> 3) & 1) == 0;
            if (i < NU) { if (jA) puA += v; else puB += v; }
            else        { if (jA) pdA += v; else pdB += v; }
        }
        pu[wp*NPV + c2]       = puA * 0.125f;
        pu[(wp+8)*NPV + c2]   = puB * 0.125f;
        pd[wp*NPV + c2]       = pdA * 0.125f;
        pd[(wp+8)*NPV + c2]   = pdB * 0.125f;
        mu[t] = smu * 0.125f;
        md[t] = smd * 0.125f;
    }
    __syncthreads();

    // ---------------- residual layers + final v layer ----------------
    // main GEMM mapping: t -> (electron group of 4, column quad)
    const int eg    = t >> 6;          // 0..3  (warp-uniform)
    const int q     = t & 63;          // column quad
    const int cA    = q * 4;
    const int ebase = eg * 4;
    // common-matvec mapping: t -> (block mu/md, k half, column quad)
    const int bh    = t >> 7;          // 0 -> mu block, 1 -> md block
    const int ckh   = t & 1;           // k half (shfl partner = lane^1)
    const int ccA   = ((t >> 1) & 63) * 4;

    for (int L = 0; L <= NFB; L++) {
        const bool isV = (L == NFB);
        const float* W    = isV ? vW : (sW + (size_t)L * SVO * NSV);
        const float* bias = isV ? vb : (sb + L * NSV);

        float puA = 0.f, puB = 0.f, pdA = 0.f, pdB = 0.f;
        if (!isV) {
            // p-stream residual layer (lane-private columns, in-place)
            const int c2 = t & 31, wp = t >> 5;
            const float* PW = pW + L * NPV * NPV + c2;
            float pw[32];
            #pragma unroll
            for (int k = 0; k < 32; k++) pw[k] = PW[k*NPV];
            const float pbias = pb[L*NPV + c2];
            for (int pr = wp; pr < 256; pr += 8) {
                float pacc = pbias;
                #pragma unroll
                for (int k = 0; k < 32; k += 4) {
                    float4 v4 = *(const float4*)(p_v + pr*NPV + k);
                    pacc += v4.x*pw[k] + v4.y*pw[k+1] + v4.z*pw[k+2] + v4.w*pw[k+3];
                }
                float v = tanh_fast(pacc) + p_v[pr*NPV + c2];
                p_v[pr*NPV + c2] = v;
                bool jA = ((pr >> 3) & 1) == 0;
                if ((pr >> 4) < NU) { if (jA) puA += v; else puB += v; }
                else                { if (jA) pdA += v; else pdB += v; }
            }
        }

        // ---- common matvec: (bh block) x (k half), 4 cols, float4 weights ----
        {
            const float* statv = (bh ? md : mu) + ckh * 128;
            const float* Wblk  = W + (size_t)(256 + bh*256 + ckh*128) * NSV + ccA;
            float c4x = 0.f, c4y = 0.f, c4z = 0.f, c4w = 0.f;
            for (int k = 0; k < 128; k += 4) {
                float4 m4 = *(const float4*)(statv + k);
                float4 w0 = *(const float4*)(Wblk + (k+0)*NSV);
                float4 w1 = *(const float4*)(Wblk + (k+1)*NSV);
                float4 w2 = *(const float4*)(Wblk + (k+2)*NSV);
                float4 w3 = *(const float4*)(Wblk + (k+3)*NSV);
                c4x += m4.x*w0.x + m4.y*w1.x + m4.z*w2.x + m4.w*w3.x;
                c4y += m4.x*w0.y + m4.y*w1.y + m4.z*w2.y + m4.w*w3.y;
                c4z += m4.x*w0.z + m4.y*w1.z + m4.z*w2.z + m4.w*w3.z;
                c4w += m4.x*w0.w + m4.y*w1.w + m4.z*w2.w + m4.w*w3.w;
            }
            c4x += __shfl_xor_sync(0xffffffffu, c4x, 1);
            c4y += __shfl_xor_sync(0xffffffffu, c4y, 1);
            c4z += __shfl_xor_sync(0xffffffffu, c4z, 1);
            c4w += __shfl_xor_sync(0xffffffffu, c4w, 1);
            if (ckh == 0) {
                float vx = c4x, vy = c4y;
                if (bh == 0) { vx += bias[ccA];   vy += bias[ccA+1]; }
                float2 cv; cv.x = vx; cv.y = vy;
                *(float2*)(com + bh*256 + ccA) = cv;
            } else {
                float vz = c4z, vw = c4w;
                if (bh == 0) { vz += bias[ccA+2]; vw += bias[ccA+3]; }
                float2 cv; cv.x = vz; cv.y = vw;
                *(float2*)(com + bh*256 + ccA + 2) = cv;
            }
        }

        // ---- main GEMM: 4 electrons x 4 adjacent cols, full k ----
        float acc0[4], acc1[4], acc2[4], acc3[4];   // acc{col}[e]
        #pragma unroll
        for (int e = 0; e < 4; e++) { acc0[e]=0.f; acc1[e]=0.f; acc2[e]=0.f; acc3[e]=0.f; }
        {
            const float* Wc = W + cA;
            const float* sv = s_v + ebase*NSV;
            for (int k = 0; k < 256; k += 4) {
                float4 w0 = *(const float4*)(Wc + (k+0)*NSV);
                float4 w1 = *(const float4*)(Wc + (k+1)*NSV);
                float4 w2 = *(const float4*)(Wc + (k+2)*NSV);
                float4 w3 = *(const float4*)(Wc + (k+3)*NSV);
                #pragma unroll
                for (int e = 0; e < 4; e++) {
                    float4 s4 = *(const float4*)(sv + e*NSV + k);
                    acc0[e] += s4.x*w0.x + s4.y*w1.x + s4.z*w2.x + s4.w*w3.x;
                    acc1[e] += s4.x*w0.y + s4.y*w1.y + s4.z*w2.y + s4.w*w3.y;
                    acc2[e] += s4.x*w0.z + s4.y*w1.z + s4.z*w2.z + s4.w*w3.z;
                    acc3[e] += s4.x*w0.w + s4.y*w1.w + s4.z*w2.w + s4.w*w3.w;
                }
            }
        }
        // ---- pu block then pd block (split to limit live weight regs) ----
        {
            const float* Wp = W + (size_t)768*NSV + cA;
            const float* pv = pu + ebase*NPV;
            for (int k = 0; k < 32; k += 4) {
                float4 w0 = *(const float4*)(Wp + (k+0)*NSV);
                float4 w1 = *(const float4*)(Wp + (k+1)*NSV);
                float4 w2 = *(const float4*)(Wp + (k+2)*NSV);
                float4 w3 = *(const float4*)(Wp + (k+3)*NSV);
                #pragma unroll
                for (int e = 0; e < 4; e++) {
                    float4 a4 = *(const float4*)(pv + e*NPV + k);
                    acc0[e] += a4.x*w0.x + a4.y*w1.x + a4.z*w2.x + a4.w*w3.x;
                    acc1[e] += a4.x*w0.y + a4.y*w1.y + a4.z*w2.y + a4.w*w3.y;
                    acc2[e] += a4.x*w0.z + a4.y*w1.z + a4.z*w2.z + a4.w*w3.z;
                    acc3[e] += a4.x*w0.w + a4.y*w1.w + a4.z*w2.w + a4.w*w3.w;
                }
            }
        }
        {
            const float* Wp = W + (size_t)800*NSV + cA;
            const float* pv = pd + ebase*NPV;
            for (int k = 0; k < 32; k += 4) {
                float4 w0 = *(const float4*)(Wp + (k+0)*NSV);
                float4 w1 = *(const float4*)(Wp + (k+1)*NSV);
                float4 w2 = *(const float4*)(Wp + (k+2)*NSV);
                float4 w3 = *(const float4*)(Wp + (k+3)*NSV);
                #pragma unroll
                for (int e = 0; e < 4; e++) {
                    float4 a4 = *(const float4*)(pv + e*NPV + k);
                    acc0[e] += a4.x*w0.x + a4.y*w1.x + a4.z*w2.x + a4.w*w3.x;
                    acc1[e] += a4.x*w0.y + a4.y*w1.y + a4.z*w2.y + a4.w*w3.y;
                    acc2[e] += a4.x*w0.z + a4.y*w1.z + a4.z*w2.z + a4.w*w3.z;
                    acc3[e] += a4.x*w0.w + a4.y*w1.w + a4.z*w2.w + a4.w*w3.w;
                }
            }
        }

        __syncthreads();   // all s_v/pu/pd/mu/md reads + com writes complete

        // ---- writeback: 4 electrons x 4 cols (float4) ----
        {
            float4 cm0 = *(const float4*)(com + cA);
            float4 cm1 = *(const float4*)(com + 256 + cA);
            const float cmx = cm0.x + cm1.x;
            const float cmy = cm0.y + cm1.y;
            const float cmz = cm0.z + cm1.z;
            const float cmw = cm0.w + cm1.w;
            if (!isV) {
                #pragma unroll
                for (int e = 0; e < 4; e++) {
                    float* dst = s_v + (ebase+e)*NSV + cA;
                    float4 old = *(const float4*)dst;
                    float4 nv;
                    nv.x = tanh_fast(acc0[e] + cmx) + old.x;
                    nv.y = tanh_fast(acc1[e] + cmy) + old.y;
                    nv.z = tanh_fast(acc2[e] + cmz) + old.z;
                    nv.w = tanh_fast(acc3[e] + cmw) + old.w;
                    *(float4*)dst = nv;
                }
                const int c2 = t & 31, wp = t >> 5;
                pu[wp*NPV + c2]     = puA * 0.125f;
                pu[(wp+8)*NPV + c2] = puB * 0.125f;
                pd[wp*NPV + c2]     = pdA * 0.125f;
                pd[(wp+8)*NPV + c2] = pdB * 0.125f;
            } else {
                #pragma unroll
                for (int e = 0; e < 4; e++) {
                    float4 nv;
                    nv.x = tanh_fast(acc0[e] + cmx);
                    nv.y = tanh_fast(acc1[e] + cmy);
                    nv.z = tanh_fast(acc2[e] + cmz);
                    nv.w = tanh_fast(acc3[e] + cmw);
                    *(float4*)(s_v + (ebase+e)*NSV + cA) = nv;
                }
                if (t < 16) {
                    const float* rg = r + b*48 + t*3;
                    float ex = rg[0], ey = rg[1], ez = rg[2];
                    float s = 0.f;
                    #pragma unroll
                    for (int atom = 0; atom < NA; atom++) {
                        float dx = ex - a[atom*3+0];
                        float dy = ey - a[atom*3+1];
                        float dz = ez - a[atom*3+2];
                        s += __expf(-sqrtf(dx*dx + dy*dy + dz*dz));
                    }
                    env[t] = s;
                }
            }
        }
        __syncthreads();

        if (!isV) {
            // ---- mu/md stats pass: thread t = column t ----
            const int c = t;
            float su = 0.f, sd2 = 0.f;
            #pragma unroll
            for (int e = 0; e < NU; e++)  su  += s_v[e*NSV + c];
            #pragma unroll
            for (int e = NU; e < NE; e++) sd2 += s_v[e*NSV + c];
            mu[c] = su * 0.125f;
            md[c] = sd2 * 0.125f;
            __syncthreads();
        }
    }
    // p_v dead; detS aliases its storage.

    // ---------------- orbitals: (spin, electron group of 4, col pair) ----------------
    {
        const int osp = t >> 7;           // spin
        const int oeg = (t >> 6) & 1;     // electron group within spin (warp-uniform)
        const int ocp = t & 63;           // col pair within 128
        const int ocA = ocp * 2;
        const float* W    = osp ? wdW : wuW;
        const float* bias = osp ? wdb : wub;
        const int eb2 = osp * 8 + oeg * 4;

        float oa0[4], oa1[4];
        #pragma unroll
        for (int ii = 0; ii < 4; ii++) { oa0[ii] = 0.f; oa1[ii] = 0.f; }
        const float* Wc2 = W + ocA;
        const float* sv2 = s_v + eb2*NSV;
        for (int k = 0; k < 256; k += 4) {
            float2 w0 = *(const float2*)(Wc2 + (k+0)*128);
            float2 w1 = *(const float2*)(Wc2 + (k+1)*128);
            float2 w2 = *(const float2*)(Wc2 + (k+2)*128);
            float2 w3 = *(const float2*)(Wc2 + (k+3)*128);
            #pragma unroll
            for (int ii = 0; ii < 4; ii++) {
                float4 s4 = *(const float4*)(sv2 + ii*NSV + k);
                oa0[ii] += s4.x*w0.x + s4.y*w1.x + s4.z*w2.x + s4.w*w3.x;
                oa1[ii] += s4.x*w0.y + s4.y*w1.y + s4.z*w2.y + s4.w*w3.y;
            }
        }
        const int col0 = ocA, col1 = ocA + 1;
        const int d0 = col0 & 15, j0 = col0 >> 4;
        const int d1 = col1 & 15, j1 = col1 >> 4;
        const int det0 = osp * NDET + d0;
        const int det1 = osp * NDET + d1;
        const float bs0 = bias[col0], bs1 = bias[col1];
        #pragma unroll
        for (int ii = 0; ii < 4; ii++) {
            const int row = oeg*4 + ii;
            const float ev = env[osp*8 + row];
            detS[det0*65 + row*8 + j0] = (oa0[ii] + bs0) * ev;
            detS[det1*65 + row*8 + j1] = (oa1[ii] + bs1) * ev;
        }
    }
    __syncthreads();

    // ---------------- slogdet: 8x8 LU with partial pivoting ----------------
    if (t < 32) {
        float* M = detS + t * 65;
        float sg = 1.f, ld = 0.f;
        for (int k = 0; k < 8; k++) {
            int p = k; float best = fabsf(M[k*8 + k]);
            for (int rr2 = k + 1; rr2 < 8; rr2++) {
                float v = fabsf(M[rr2*8 + k]);
                if (v > best) { best = v; p = rr2; }
            }
            if (p != k) {
                for (int cc = 0; cc < 8; cc++) {
                    float tmp = M[k*8 + cc]; M[k*8 + cc] = M[p*8 + cc]; M[p*8 + cc] = tmp;
                }
                sg = -sg;
            }
            float piv = M[k*8 + k];
            if (piv < 0.f) sg = -sg;
            ld += logf(fabsf(piv));
            float inv = 1.f / piv;
            for (int rr2 = k + 1; rr2 < 8; rr2++) {
                float f = M[rr2*8 + k] * inv;
                for (int cc = k + 1; cc < 8; cc++) M[rr2*8 + cc] -= f * M[k*8 + cc];
            }
        }
        logd_s[t] = ld; sign_s[t] = sg;
    }
    __syncthreads();

    // ---------------- combine ----------------
    if (t == 0) {
        float lds[NDET], sgs[NDET], m = -1e30f;
        #pragma unroll
        for (int d = 0; d < NDET; d++) {
            lds[d] = logd_s[d] + logd_s[NDET + d];
            sgs[d] = sign_s[d] * sign_s[NDET + d];
            if (lds[d] > m) m = lds[d];
        }
        float sum = 0.f;
        #pragma unroll
        for (int d = 0; d < NDET; d++)
            sum += sgs[d] * expf(lds[d] - m) * wfW[d];
        out[b] = logf(fabsf(sum)) + m;
    }
}

extern "C" void kernel_launch(void* const* d_in, const int* in_sizes, int n_in,
                              void* d_out, int out_size)
{
    const float* r   = (const float*)d_in[0];
    const float* a   = (const float*)d_in[1];
    const float* sW0 = (const float*)d_in[2];
    const float* sb0 = (const float*)d_in[3];
    const float* sW  = (const float*)d_in[4];
    const float* sb  = (const float*)d_in[5];
    const float* pW0 = (const float*)d_in[6];
    const float* pb0 = (const float*)d_in[7];
    const float* pW  = (const float*)d_in[8];
    const float* pb  = (const float*)d_in[9];
    const float* vW  = (const float*)d_in[10];
    const float* vb  = (const float*)d_in[11];
    const float* wuW = (const float*)d_in[12];
    const float* wub = (const float*)d_in[13];
    const float* wdW = (const float*)d_in[14];
    const float* wdb = (const float*)d_in[15];
    const float* wfW = (const float*)d_in[16];
    float* out = (float*)d_out;

    const int B = in_sizes[0] / (NE * 3);

    cudaFuncSetAttribute(ansatz_kernel,
                         cudaFuncAttributeMaxDynamicSharedMemorySize, SMEM_BYTES);
    ansatz_kernel<<<B, 256, SMEM_BYTES>>>(r, a, sW0, sb0, sW, sb, pW0, pb0,
                                          pW, pb, vW, vb, wuW, wub, wdW, wdb,
                                          wfW, out);
}